// round 1
// baseline (speedup 1.0000x reference)
#include <cuda_runtime.h>

#define BB   4
#define CINC 64
#define COUTC 64
#define KNB  16
#define NN   32768
#define PTS  64      // points per block
#define VROW 260     // padded row stride for Vs (words), 16B-aligned-friendly

// ---- scratch (no allocations allowed) ----
__device__ float  g_featT[(size_t)BB * NN * CINC];   // [b][n][c]  33.5 MB
__device__ float4 g_posT [(size_t)BB * NN];          // [b][n] xyz_   2 MB
__device__ int    g_nbT  [(size_t)BB * NN * KNB];    // [b][n][k]   8.4 MB

// ---------------------------------------------------------------------------
// Kernel 1a: transpose features [B][CIN][N] -> [B][N][CIN]
// ---------------------------------------------------------------------------
__global__ void transpose_feat(const float* __restrict__ f) {
    __shared__ float tile[32][33];
    const int b  = blockIdx.z;
    const int c0 = blockIdx.y * 32;
    const int n0 = blockIdx.x * 32;
    const float* src = f + (size_t)b * CINC * NN;
    #pragma unroll
    for (int dy = threadIdx.y; dy < 32; dy += 8)
        tile[dy][threadIdx.x] = src[(size_t)(c0 + dy) * NN + n0 + threadIdx.x];
    __syncthreads();
    float* dst = g_featT + (size_t)b * NN * CINC;
    #pragma unroll
    for (int dy = threadIdx.y; dy < 32; dy += 8)
        dst[(size_t)(n0 + dy) * CINC + c0 + threadIdx.x] = tile[threadIdx.x][dy];
}

// ---------------------------------------------------------------------------
// Kernel 1b: positions [B][3][N] -> float4 rows; neighborhood [B][K][N] -> [b][n][k]
// ---------------------------------------------------------------------------
__global__ void prep_pos_nb(const float* __restrict__ pos, const int* __restrict__ nb) {
    const int t = blockIdx.x * blockDim.x + threadIdx.x;   // over B*N
    const int b = t / NN;
    const int n = t - b * NN;
    const float* p = pos + (size_t)b * 3 * NN;
    g_posT[t] = make_float4(p[n], p[NN + n], p[2 * NN + n], 0.f);
    const int* s = nb + (size_t)b * KNB * NN;
    int* d = g_nbT + (size_t)t * KNB;
    #pragma unroll
    for (int k = 0; k < KNB; k++) d[k] = s[(size_t)k * NN + n];
}

// ---------------------------------------------------------------------------
// Kernel 2: fused gather-reduce + GEMM
//   phase 1: per block, build V[64 pts][256] in shared
//            (cc = d*64+c : d=0..2 -> S[d][c], d=3 -> fsum[c])
//   phase 2: C[64 pts][64 outs] = V @ W4, 4x4 register tiles, +bias
// ---------------------------------------------------------------------------
__global__ void __launch_bounds__(256, 1) flexconv_main(
    const float* __restrict__ wt,    // [3][CIN][COUT]
    const float* __restrict__ wb,    // [CIN][COUT]
    const float* __restrict__ bias,  // [COUT]
    float* __restrict__ out)         // [B][COUT][N]
{
    extern __shared__ float smem[];
    float* Vs  = smem;               // [PTS][VROW]
    float* W4s = smem + PTS * VROW;  // [256][64]

    const int tid = threadIdx.x;
    const int b   = blockIdx.y;
    const int n0  = blockIdx.x * PTS;

    // stage W4 = [theta(3*64) ; bias_w(64)][64] — source layouts are already [cc][o]
    #pragma unroll
    for (int i = 0; i < 64; i++) {
        int q = tid + i * 256;
        W4s[q] = (q < 3 * CINC * COUTC) ? wt[q] : wb[q - 3 * CINC * COUTC];
    }

    // ---------------- phase 1: gather + neighbor reduction ----------------
    const int w = tid >> 5, l = tid & 31;
    const float2* featT2 = (const float2*)g_featT;       // [(b*N+idx)*32 + l]
    const float4* posT   = g_posT + (size_t)b * NN;

    #pragma unroll 1
    for (int i = 0; i < 8; i++) {
        const int p = w * 8 + i;
        const int n = n0 + p;
        const int* nbrow = g_nbT + ((size_t)b * NN + n) * KNB;
        int myidx = nbrow[l & 15];
        const float4 ps = __ldg(&posT[n]);
        float2 v0 = make_float2(0.f, 0.f), v1 = v0, v2 = v0, v3 = v0;
        #pragma unroll
        for (int k = 0; k < KNB; k++) {
            int idx = __shfl_sync(0xffffffffu, myidx, k);
            float4 pg = __ldg(&posT[idx]);
            float2 fv = __ldg(&featT2[((size_t)b * NN + idx) * 32 + l]);
            float dx = pg.x - ps.x, dy = pg.y - ps.y, dz = pg.z - ps.z;
            v0.x += dx * fv.x; v0.y += dx * fv.y;
            v1.x += dy * fv.x; v1.y += dy * fv.y;
            v2.x += dz * fv.x; v2.y += dz * fv.y;
            v3.x += fv.x;      v3.y += fv.y;
        }
        float* vrow = Vs + p * VROW;                      // cc = d*64 + 2l
        ((float2*)(vrow + 0 * 64))[l] = v0;
        ((float2*)(vrow + 1 * 64))[l] = v1;
        ((float2*)(vrow + 2 * 64))[l] = v2;
        ((float2*)(vrow + 3 * 64))[l] = v3;
    }
    __syncthreads();

    // ---------------- phase 2: GEMM 64x64 = V[64x256] @ W4[256x64] --------
    const int tx = tid & 15;         // output group: o = 4*tx + j
    const int ty = tid >> 4;         // point group:  p = 4*ty + i
    const float4 bv = __ldg(&((const float4*)bias)[tx]);

    float acc[4][4];
    #pragma unroll
    for (int i = 0; i < 4; i++) {
        acc[i][0] = bv.x; acc[i][1] = bv.y; acc[i][2] = bv.z; acc[i][3] = bv.w;
    }

    const float* vbase = Vs + (4 * ty) * VROW;
    const float* wbase = W4s + 4 * tx;
    #pragma unroll 8
    for (int ch = 0; ch < 256; ch++) {
        float4 wv = *(const float4*)&wbase[ch * 64];
        float a0 = vbase[0 * VROW + ch];
        float a1 = vbase[1 * VROW + ch];
        float a2 = vbase[2 * VROW + ch];
        float a3 = vbase[3 * VROW + ch];
        acc[0][0] += a0 * wv.x; acc[0][1] += a0 * wv.y; acc[0][2] += a0 * wv.z; acc[0][3] += a0 * wv.w;
        acc[1][0] += a1 * wv.x; acc[1][1] += a1 * wv.y; acc[1][2] += a1 * wv.z; acc[1][3] += a1 * wv.w;
        acc[2][0] += a2 * wv.x; acc[2][1] += a2 * wv.y; acc[2][2] += a2 * wv.z; acc[2][3] += a2 * wv.w;
        acc[3][0] += a3 * wv.x; acc[3][1] += a3 * wv.y; acc[3][2] += a3 * wv.z; acc[3][3] += a3 * wv.w;
    }

    // store: out[b][o][n], 4 consecutive points per thread -> float4
    float* ob = out + (size_t)b * COUTC * NN + n0 + 4 * ty;
    #pragma unroll
    for (int j = 0; j < 4; j++) {
        float4 r = make_float4(acc[0][j], acc[1][j], acc[2][j], acc[3][j]);
        *(float4*)&ob[(size_t)(4 * tx + j) * NN] = r;
    }
}

// ---------------------------------------------------------------------------
extern "C" void kernel_launch(void* const* d_in, const int* in_sizes, int n_in,
                              void* d_out, int out_size) {
    const float* feat = (const float*)d_in[0];   // [B][CIN][N]
    const float* wt   = (const float*)d_in[1];   // [3][CIN][COUT]
    const float* wb   = (const float*)d_in[2];   // [CIN][COUT]
    const float* bias = (const float*)d_in[3];   // [COUT]
    const int*   nb   = (const int*)  d_in[4];   // [B][K][N]
    const float* pos  = (const float*)d_in[5];   // [B][3][N]
    float* out = (float*)d_out;

    dim3 g1(NN / 32, CINC / 32, BB), b1(32, 8);
    transpose_feat<<<g1, b1>>>(feat);
    prep_pos_nb<<<(BB * NN) / 256, 256>>>(pos, nb);

    const int smem_bytes = (PTS * VROW + 256 * 64) * (int)sizeof(float); // ~132 KB
    cudaFuncSetAttribute(flexconv_main,
                         cudaFuncAttributeMaxDynamicSharedMemorySize, smem_bytes);
    flexconv_main<<<dim3(NN / PTS, BB), 256, smem_bytes>>>(wt, wb, bias, out);
}

// round 3
// speedup vs baseline: 1.6630x; 1.6630x over previous
#include <cuda_runtime.h>
#include <cstdint>

#define BB      4
#define CINC    64
#define COUTC   64
#define KNB     16
#define NN      32768
#define PTS     128       // points per CTA (= GEMM M)
#define VROW    260       // V row stride (words): A-frag LDS conflict-free
#define WSTR    72        // W4 row stride (words): B-frag LDS conflict-free
#define THREADS 512

// ---- scratch (no allocations allowed) ----
__device__ float  g_featT[(size_t)BB * NN * CINC];   // [b][n][c]
__device__ float4 g_posT [(size_t)BB * NN];          // [b][n] xyz_
__device__ int    g_nbT  [(size_t)BB * NN * KNB];    // [b][n][k]

__device__ __forceinline__ uint32_t f32_to_tf32(float x) {
    uint32_t r;
    asm("cvt.rna.tf32.f32 %0, %1;" : "=r"(r) : "f"(x));
    return r;
}

// m16n8k8 tf32 MMA (sm_80+ PTX, HMMA on sm_103a)
__device__ __forceinline__ void mma_tf32(float d[4],
    uint32_t a0, uint32_t a1, uint32_t a2, uint32_t a3,
    uint32_t b0, uint32_t b1)
{
    asm volatile(
        "mma.sync.aligned.m16n8k8.row.col.f32.tf32.tf32.f32 "
        "{%0,%1,%2,%3}, {%4,%5,%6,%7}, {%8,%9}, {%0,%1,%2,%3};"
        : "+f"(d[0]), "+f"(d[1]), "+f"(d[2]), "+f"(d[3])
        : "r"(a0), "r"(a1), "r"(a2), "r"(a3), "r"(b0), "r"(b1));
}

// smem layout (32-bit words)
static constexpr int SW_W4   = 0;                       // [256][WSTR]
static constexpr int SW_VS   = 256 * WSTR;              // [PTS][VROW]
static constexpr int SW_BIAS = SW_VS + PTS * VROW;      // [64]
static constexpr int SMEM_WORDS = SW_BIAS + 64;
static constexpr int SMEM_BYTES = SMEM_WORDS * 4;       // ~207.6 KB

// ---------------------------------------------------------------------------
// Kernel 1a: transpose features [B][CIN][N] -> [B][N][CIN]
// ---------------------------------------------------------------------------
__global__ void transpose_feat(const float* __restrict__ f) {
    __shared__ float tile[32][33];
    const int b  = blockIdx.z;
    const int c0 = blockIdx.y * 32;
    const int n0 = blockIdx.x * 32;
    const float* src = f + (size_t)b * CINC * NN;
    #pragma unroll
    for (int dy = threadIdx.y; dy < 32; dy += 8)
        tile[dy][threadIdx.x] = src[(size_t)(c0 + dy) * NN + n0 + threadIdx.x];
    __syncthreads();
    float* dst = g_featT + (size_t)b * NN * CINC;
    #pragma unroll
    for (int dy = threadIdx.y; dy < 32; dy += 8)
        dst[(size_t)(n0 + dy) * CINC + c0 + threadIdx.x] = tile[threadIdx.x][dy];
}

// ---------------------------------------------------------------------------
// Kernel 1b: positions -> float4 rows; neighborhood -> [b][n][k]
// ---------------------------------------------------------------------------
__global__ void prep_pos_nb(const float* __restrict__ pos, const int* __restrict__ nb) {
    const int t = blockIdx.x * blockDim.x + threadIdx.x;   // over B*N
    const int b = t / NN;
    const int n = t - b * NN;
    const float* p = pos + (size_t)b * 3 * NN;
    g_posT[t] = make_float4(p[n], p[NN + n], p[2 * NN + n], 0.f);
    const int* s = nb + (size_t)b * KNB * NN;
    int* d = g_nbT + (size_t)t * KNB;
    #pragma unroll
    for (int k = 0; k < KNB; k++) d[k] = s[(size_t)k * NN + n];
}

// ---------------------------------------------------------------------------
// Main: gather+reduce -> V(tf32, smem) -> mma.sync tf32 GEMM -> epilogue
//   V[p][cc], cc = d*64 + c : d=0..2 -> S[d][c], d=3 -> fsum[c]
//   W4[cc][o] = [theta(192 rows); wb(64 rows)]
// ---------------------------------------------------------------------------
__global__ void __launch_bounds__(THREADS, 1) flexconv_main(
    const float* __restrict__ wt,    // [3][CIN][COUT]
    const float* __restrict__ wb,    // [CIN][COUT]
    const float* __restrict__ bias,  // [COUT]
    float* __restrict__ out)         // [B][COUT][N]
{
    extern __shared__ uint32_t smw[];
    uint32_t* W4s = smw + SW_W4;
    uint32_t* Vs  = smw + SW_VS;
    float*    bs  = (float*)(smw + SW_BIAS);

    const int tid = threadIdx.x;
    const int w   = tid >> 5, l = tid & 31;
    const int b   = blockIdx.y;
    const int n0  = blockIdx.x * PTS;

    if (tid < COUTC) bs[tid] = bias[tid];

    // stage W4 -> [k][o] with stride WSTR, converted to tf32 (coalesced over o)
    #pragma unroll
    for (int it = 0; it < (256 * 64) / THREADS; it++) {
        int t = tid + it * THREADS;
        int k = t >> 6, o = t & 63;
        float v = (k < 192) ? wt[t] : wb[t - 192 * 64];
        W4s[k * WSTR + o] = f32_to_tf32(v);
    }

    // ---------------- phase 1: gather + neighbor reduction ----------------
    const float2* featT2 = (const float2*)g_featT;        // [(b*N+idx)*32 + l]
    const float4* posT   = g_posT + (size_t)b * NN;

    #pragma unroll 1
    for (int i = 0; i < 8; i++) {                         // 16 warps x 8 points
        const int p = w * 8 + i;
        const int n = n0 + p;
        const int* nbrow = g_nbT + ((size_t)b * NN + n) * KNB;
        int myidx = nbrow[l & 15];
        const float4 ps = __ldg(&posT[n]);
        float2 v0 = make_float2(0.f, 0.f), v1 = v0, v2 = v0, v3 = v0;
        #pragma unroll
        for (int k = 0; k < KNB; k++) {
            int idx = __shfl_sync(0xffffffffu, myidx, k);
            float4 pg = __ldg(&posT[idx]);
            float2 fv = __ldg(&featT2[((size_t)b * NN + idx) * 32 + l]);
            float dx = pg.x - ps.x, dy = pg.y - ps.y, dz = pg.z - ps.z;
            v0.x += dx * fv.x; v0.y += dx * fv.y;
            v1.x += dy * fv.x; v1.y += dy * fv.y;
            v2.x += dz * fv.x; v2.y += dz * fv.y;
            v3.x += fv.x;      v3.y += fv.y;
        }
        uint32_t* vrow = Vs + p * VROW;                   // cc = d*64 + 2l
        vrow[0 * 64 + 2 * l] = f32_to_tf32(v0.x);  vrow[0 * 64 + 2 * l + 1] = f32_to_tf32(v0.y);
        vrow[1 * 64 + 2 * l] = f32_to_tf32(v1.x);  vrow[1 * 64 + 2 * l + 1] = f32_to_tf32(v1.y);
        vrow[2 * 64 + 2 * l] = f32_to_tf32(v2.x);  vrow[2 * 64 + 2 * l + 1] = f32_to_tf32(v2.y);
        vrow[3 * 64 + 2 * l] = f32_to_tf32(v3.x);  vrow[3 * 64 + 2 * l + 1] = f32_to_tf32(v3.y);
    }
    __syncthreads();

    // ---------------- phase 2: tf32 tensor GEMM 128x64x256 -----------------
    // warp tile: m16 (mw) x n32 (nh), full K. 4 n8-tiles per warp.
    const int mw = w & 7;            // M tile index
    const int nh = w >> 3;           // N half index
    const int r  = l >> 2, c = l & 3;

    float acc[4][4];
    #pragma unroll
    for (int t = 0; t < 4; t++)
        acc[t][0] = acc[t][1] = acc[t][2] = acc[t][3] = 0.f;

    const uint32_t* Va = Vs + (16 * mw + r) * VROW + c;   // +0 / +8*VROW rows
    const uint32_t* Wb = W4s + 32 * nh + r;               // [k][o]

    #pragma unroll 4
    for (int k0 = 0; k0 < 256; k0 += 8) {
        uint32_t a0 = Va[k0];
        uint32_t a1 = Va[8 * VROW + k0];
        uint32_t a2 = Va[k0 + 4];
        uint32_t a3 = Va[8 * VROW + k0 + 4];
        const uint32_t* wk0 = Wb + (k0 + c) * WSTR;
        const uint32_t* wk1 = Wb + (k0 + c + 4) * WSTR;
        #pragma unroll
        for (int t = 0; t < 4; t++)
            mma_tf32(acc[t], a0, a1, a2, a3, wk0[8 * t], wk1[8 * t]);
    }

    // ---------------- epilogue: bias + store --------------------------------
    float* op = out + (size_t)b * COUTC * NN + n0 + 16 * mw + r;
    #pragma unroll
    for (int t = 0; t < 4; t++) {
        int o0 = 32 * nh + 8 * t + 2 * c;
        float bv0 = bs[o0], bv1 = bs[o0 + 1];
        op[(size_t)o0 * NN]           = acc[t][0] + bv0;
        op[(size_t)(o0 + 1) * NN]     = acc[t][1] + bv1;
        op[(size_t)o0 * NN + 8]       = acc[t][2] + bv0;
        op[(size_t)(o0 + 1) * NN + 8] = acc[t][3] + bv1;
    }
}

// ---------------------------------------------------------------------------
extern "C" void kernel_launch(void* const* d_in, const int* in_sizes, int n_in,
                              void* d_out, int out_size) {
    const float* feat = (const float*)d_in[0];   // [B][CIN][N]
    const float* wt   = (const float*)d_in[1];   // [3][CIN][COUT]
    const float* wb   = (const float*)d_in[2];   // [CIN][COUT]
    const float* bias = (const float*)d_in[3];   // [COUT]
    const int*   nb   = (const int*)  d_in[4];   // [B][K][N]
    const float* pos  = (const float*)d_in[5];   // [B][3][N]
    float* out = (float*)d_out;

    dim3 g1(NN / 32, CINC / 32, BB), b1(32, 8);
    transpose_feat<<<g1, b1>>>(feat);
    prep_pos_nb<<<(BB * NN) / 256, 256>>>(pos, nb);

    cudaFuncSetAttribute(flexconv_main,
                         cudaFuncAttributeMaxDynamicSharedMemorySize, SMEM_BYTES);
    flexconv_main<<<dim3(NN / PTS, BB), THREADS, SMEM_BYTES>>>(wt, wb, bias, out);
}

// round 4
// speedup vs baseline: 1.8330x; 1.1022x over previous
#include <cuda_runtime.h>
#include <cstdint>

#define BB      4
#define CINC    64
#define COUTC   64
#define KNB     16
#define NN      32768
#define PTS     128       // points per CTA (= GEMM M)
#define VROW    260       // V row stride (words): A-frag LDS conflict-free
#define WSTR    72        // W4 row stride (words): B-frag LDS conflict-free
#define THREADS 1024

// ---- scratch (no allocations allowed) ----
__device__ float  g_featT[(size_t)BB * NN * CINC];   // [b][n][c]
__device__ float4 g_posT [(size_t)BB * NN];          // [b][n] xyz_
__device__ int    g_nbT  [(size_t)BB * NN * KNB];    // [b][n][k]

__device__ __forceinline__ uint32_t f32_to_tf32(float x) {
    uint32_t r;
    asm("cvt.rna.tf32.f32 %0, %1;" : "=r"(r) : "f"(x));
    return r;
}

// m16n8k8 tf32 MMA (sm_80+ PTX, HMMA on sm_103a)
__device__ __forceinline__ void mma_tf32(float d[4],
    uint32_t a0, uint32_t a1, uint32_t a2, uint32_t a3,
    uint32_t b0, uint32_t b1)
{
    asm volatile(
        "mma.sync.aligned.m16n8k8.row.col.f32.tf32.tf32.f32 "
        "{%0,%1,%2,%3}, {%4,%5,%6,%7}, {%8,%9}, {%0,%1,%2,%3};"
        : "+f"(d[0]), "+f"(d[1]), "+f"(d[2]), "+f"(d[3])
        : "r"(a0), "r"(a1), "r"(a2), "r"(a3), "r"(b0), "r"(b1));
}

// smem layout (32-bit words)
static constexpr int SW_W4   = 0;                       // [256][WSTR]
static constexpr int SW_VS   = 256 * WSTR;              // [PTS][VROW]
static constexpr int SW_BIAS = SW_VS + PTS * VROW;      // [64]
static constexpr int SMEM_WORDS = SW_BIAS + 64;
static constexpr int SMEM_BYTES = SMEM_WORDS * 4;       // ~207.6 KB

// ---------------------------------------------------------------------------
// Kernel 1a: transpose features [B][CIN][N] -> [B][N][CIN], 64x64 float4 tiles
// ---------------------------------------------------------------------------
__global__ void __launch_bounds__(256) transpose_feat(const float4* __restrict__ f4) {
    __shared__ float tile[64][65];
    const int b  = blockIdx.y;
    const int n0 = blockIdx.x * 64;
    const int tx = threadIdx.x & 15;       // n-quad within tile
    const int ty = threadIdx.x >> 4;       // 0..15
    const float4* src = f4 + (size_t)b * CINC * (NN / 4) + (n0 >> 2);
    #pragma unroll
    for (int cc = ty; cc < 64; cc += 16) {
        float4 v = __ldg(&src[(size_t)cc * (NN / 4) + tx]);
        tile[4 * tx + 0][cc] = v.x;
        tile[4 * tx + 1][cc] = v.y;
        tile[4 * tx + 2][cc] = v.z;
        tile[4 * tx + 3][cc] = v.w;
    }
    __syncthreads();
    float4* dst = (float4*)(g_featT + (size_t)b * NN * CINC) + (size_t)n0 * 16;
    #pragma unroll
    for (int rr = ty; rr < 64; rr += 16) {
        float4 v = make_float4(tile[rr][4 * tx], tile[rr][4 * tx + 1],
                               tile[rr][4 * tx + 2], tile[rr][4 * tx + 3]);
        dst[(size_t)rr * 16 + tx] = v;
    }
}

// ---------------------------------------------------------------------------
// Kernel 1b: positions -> float4 rows; neighborhood -> [b][n][k]
// ---------------------------------------------------------------------------
__global__ void prep_pos_nb(const float* __restrict__ pos, const int* __restrict__ nb) {
    const int t = blockIdx.x * blockDim.x + threadIdx.x;   // over B*N
    const int b = t / NN;
    const int n = t - b * NN;
    const float* p = pos + (size_t)b * 3 * NN;
    g_posT[t] = make_float4(p[n], p[NN + n], p[2 * NN + n], 0.f);
    const int* s = nb + (size_t)b * KNB * NN;
    int* d = g_nbT + (size_t)t * KNB;
    #pragma unroll
    for (int k = 0; k < KNB; k++) d[k] = s[(size_t)k * NN + n];
}

// ---------------------------------------------------------------------------
// Main: gather+reduce -> V(tf32, smem) -> mma.sync tf32 GEMM -> epilogue
//   V[p][cc], cc = d*64 + c : d=0..2 -> S[d][c], d=3 -> fsum[c]
//   W4[cc][o] = [theta(192 rows); wb(64 rows)]
// ---------------------------------------------------------------------------
__global__ void __launch_bounds__(THREADS, 1) flexconv_main(
    const float* __restrict__ wt,    // [3][CIN][COUT]
    const float* __restrict__ wb,    // [CIN][COUT]
    const float* __restrict__ bias,  // [COUT]
    float* __restrict__ out)         // [B][COUT][N]
{
    extern __shared__ uint32_t smw[];
    uint32_t* W4s = smw + SW_W4;
    uint32_t* Vs  = smw + SW_VS;
    float*    bs  = (float*)(smw + SW_BIAS);

    const int tid = threadIdx.x;
    const int w   = tid >> 5, l = tid & 31;
    const int b   = blockIdx.y;
    const int n0  = blockIdx.x * PTS;

    if (tid < COUTC) bs[tid] = bias[tid];

    // stage W4 -> [k][o] with stride WSTR, converted to tf32 (coalesced over o)
    #pragma unroll
    for (int it = 0; it < (256 * 64) / THREADS; it++) {
        int t = tid + it * THREADS;
        int k = t >> 6, o = t & 63;
        float v = (k < 192) ? wt[t] : wb[t - 192 * 64];
        W4s[k * WSTR + o] = f32_to_tf32(v);
    }

    // ---------------- phase 1: gather + neighbor reduction ----------------
    const float2* featT2 = (const float2*)g_featT;        // [(b*N+idx)*32 + l]
    const float4* posT   = g_posT + (size_t)b * NN;

    #pragma unroll 1
    for (int i = 0; i < 4; i++) {                         // 32 warps x 4 points
        const int p = w * 4 + i;
        const int n = n0 + p;
        const int* nbrow = g_nbT + ((size_t)b * NN + n) * KNB;
        int myidx = nbrow[l & 15];
        const float4 ps = __ldg(&posT[n]);
        float2 v0 = make_float2(0.f, 0.f), v1 = v0, v2 = v0, v3 = v0;
        #pragma unroll
        for (int k = 0; k < KNB; k++) {
            int idx = __shfl_sync(0xffffffffu, myidx, k);
            float4 pg = __ldg(&posT[idx]);
            float2 fv = __ldg(&featT2[((size_t)b * NN + idx) * 32 + l]);
            float dx = pg.x - ps.x, dy = pg.y - ps.y, dz = pg.z - ps.z;
            v0.x += dx * fv.x; v0.y += dx * fv.y;
            v1.x += dy * fv.x; v1.y += dy * fv.y;
            v2.x += dz * fv.x; v2.y += dz * fv.y;
            v3.x += fv.x;      v3.y += fv.y;
        }
        uint32_t* vrow = Vs + p * VROW;                   // cc = d*64 + 2l
        vrow[0 * 64 + 2 * l] = f32_to_tf32(v0.x);  vrow[0 * 64 + 2 * l + 1] = f32_to_tf32(v0.y);
        vrow[1 * 64 + 2 * l] = f32_to_tf32(v1.x);  vrow[1 * 64 + 2 * l + 1] = f32_to_tf32(v1.y);
        vrow[2 * 64 + 2 * l] = f32_to_tf32(v2.x);  vrow[2 * 64 + 2 * l + 1] = f32_to_tf32(v2.y);
        vrow[3 * 64 + 2 * l] = f32_to_tf32(v3.x);  vrow[3 * 64 + 2 * l + 1] = f32_to_tf32(v3.y);
    }
    __syncthreads();

    // ---------------- phase 2: tf32 tensor GEMM 128x64x256 -----------------
    // 32 warps: warp tile m16 x n16, full K. 2 n8-tiles per warp.
    const int mw = w & 7;            // M tile index (8 tiles x 16 rows)
    const int nq = w >> 3;           // N quarter index (4 x 16 cols)
    const int r  = l >> 2, c = l & 3;

    float acc[2][4];
    #pragma unroll
    for (int t = 0; t < 2; t++)
        acc[t][0] = acc[t][1] = acc[t][2] = acc[t][3] = 0.f;

    const uint32_t* Va = Vs + (16 * mw + r) * VROW + c;   // +0 / +8*VROW rows
    const uint32_t* Wb = W4s + 16 * nq + r;               // [k][o]

    #pragma unroll 8
    for (int k0 = 0; k0 < 256; k0 += 8) {
        uint32_t a0 = Va[k0];
        uint32_t a1 = Va[8 * VROW + k0];
        uint32_t a2 = Va[k0 + 4];
        uint32_t a3 = Va[8 * VROW + k0 + 4];
        const uint32_t* wk0 = Wb + (k0 + c) * WSTR;
        const uint32_t* wk1 = Wb + (k0 + c + 4) * WSTR;
        #pragma unroll
        for (int t = 0; t < 2; t++)
            mma_tf32(acc[t], a0, a1, a2, a3, wk0[8 * t], wk1[8 * t]);
    }

    // ---------------- epilogue: bias + store --------------------------------
    float* op = out + (size_t)b * COUTC * NN + n0 + 16 * mw + r;
    #pragma unroll
    for (int t = 0; t < 2; t++) {
        int o0 = 16 * nq + 8 * t + 2 * c;
        float bv0 = bs[o0], bv1 = bs[o0 + 1];
        op[(size_t)o0 * NN]           = acc[t][0] + bv0;
        op[(size_t)(o0 + 1) * NN]     = acc[t][1] + bv1;
        op[(size_t)o0 * NN + 8]       = acc[t][2] + bv0;
        op[(size_t)(o0 + 1) * NN + 8] = acc[t][3] + bv1;
    }
}

// ---------------------------------------------------------------------------
extern "C" void kernel_launch(void* const* d_in, const int* in_sizes, int n_in,
                              void* d_out, int out_size) {
    const float* feat = (const float*)d_in[0];   // [B][CIN][N]
    const float* wt   = (const float*)d_in[1];   // [3][CIN][COUT]
    const float* wb   = (const float*)d_in[2];   // [CIN][COUT]
    const float* bias = (const float*)d_in[3];   // [COUT]
    const int*   nb   = (const int*)  d_in[4];   // [B][K][N]
    const float* pos  = (const float*)d_in[5];   // [B][3][N]
    float* out = (float*)d_out;

    transpose_feat<<<dim3(NN / 64, BB), 256>>>((const float4*)feat);
    prep_pos_nb<<<(BB * NN) / 256, 256>>>(pos, nb);

    cudaFuncSetAttribute(flexconv_main,
                         cudaFuncAttributeMaxDynamicSharedMemorySize, SMEM_BYTES);
    flexconv_main<<<dim3(NN / PTS, BB), THREADS, SMEM_BYTES>>>(wt, wb, bias, out);
}